// round 1
// baseline (speedup 1.0000x reference)
#include <cuda_runtime.h>

// InnerProduct: ip[r,p] = sum_f w[p,f]^2 * sum_e x[r,f,e]^2
// x: [32768, 64, 128] f32  (d_in[0])
// w: [10, 64] f32          (d_in[1])
// out: [32768, 10] f32
//
// Memory-bound: 1 GiB read of x. One CTA per row; each warp covers 8 fields,
// one field per iteration with a fully coalesced 512B warp read (LDG.128).

#define BATCH    32768
#define N_FIELDS 64
#define EMBED    128
#define OUT_SZ   10
#define THREADS  256

__global__ __launch_bounds__(THREADS, 1)
void innerproduct_kernel(const float* __restrict__ x,
                         const float* __restrict__ w,
                         float* __restrict__ out)
{
    const int r    = blockIdx.x;
    const int tid  = threadIdx.x;
    const int warp = tid >> 5;
    const int lane = tid & 31;

    __shared__ float xsq[N_FIELDS];

    // Row base: r * 64 * 128 floats = r * 2048 float4s
    const float4* __restrict__ xr =
        reinterpret_cast<const float4*>(x) + (size_t)r * (N_FIELDS * EMBED / 4);

    // Warp `warp` handles fields f = warp + 8*i, i = 0..7.
    // Lane `lane` loads float4 #lane of that field (32 float4 = 128 floats).
    float acc[8];
#pragma unroll
    for (int i = 0; i < 8; i++) {
        float4 v = xr[(warp + 8 * i) * (EMBED / 4) + lane];
        acc[i] = v.x * v.x + v.y * v.y + v.z * v.z + v.w * v.w;
    }

    // Full-warp butterfly reduce each of the 8 per-field partials.
#pragma unroll
    for (int i = 0; i < 8; i++) {
#pragma unroll
        for (int s = 16; s >= 1; s >>= 1)
            acc[i] += __shfl_xor_sync(0xffffffffu, acc[i], s);
    }
    if (lane == 0) {
#pragma unroll
        for (int i = 0; i < 8; i++)
            xsq[warp + 8 * i] = acc[i];
    }
    __syncthreads();

    // Tail: 10 outputs, 16 threads per output (warps 0..4 fully active).
    if (tid < OUT_SZ * 16) {
        const int p = tid >> 4;   // output index 0..9
        const int g = tid & 15;   // sub-lane within the 16-group
        float s = 0.f;
#pragma unroll
        for (int k = 0; k < 4; k++) {
            const int f = g * 4 + k;
            float wv = __ldg(&w[p * N_FIELDS + f]);
            s = fmaf(xsq[f], wv * wv, s);
        }
        // Reduce the 16-lane group (contiguous lanes within a warp).
#pragma unroll
        for (int sh = 8; sh >= 1; sh >>= 1)
            s += __shfl_xor_sync(0xffffffffu, s, sh);
        if (g == 0)
            out[r * OUT_SZ + p] = s;
    }
}

extern "C" void kernel_launch(void* const* d_in, const int* in_sizes, int n_in,
                              void* d_out, int out_size)
{
    const float* x = (const float*)d_in[0];
    const float* w = (const float*)d_in[1];
    float* out = (float*)d_out;

    innerproduct_kernel<<<BATCH, THREADS>>>(x, w, out);
}